// round 9
// baseline (speedup 1.0000x reference)
#include <cuda_runtime.h>
#include <cstdint>

#define BATCH 8
#define CCH   48
#define NPIX  4096
#define NB    32768
#define KNN   9

// ---------------- device scratch ----------------
__device__ float  g_xt [BATCH * CCH * NPIX];   // normalized, k-major (B tiles)
__device__ float2 g_xtd[BATCH * CCH * NPIX];   // normalized, duplicated pairs (A tiles)
__device__ float4 g_nodes[NB * 12];            // raw, node-major (k5)
__device__ float  g_sq[NB];                    // sum(xn^2)
__device__ int    g_knn[NB * KNN];
__device__ int    g_deg[NB];

// ---------------- helpers ----------------
__device__ __forceinline__ uint32_t smem_u32(const void* p) {
    uint32_t a;
    asm("{ .reg .u64 t; cvta.to.shared.u64 t, %1; cvt.u32.u64 %0, t; }" : "=r"(a) : "l"(p));
    return a;
}
__device__ __forceinline__ void cp16(uint32_t dst, const void* src) {
    asm volatile("cp.async.cg.shared.global [%0], [%1], 16;" :: "r"(dst), "l"(src));
}
__device__ __forceinline__ void cp4(uint32_t dst, const void* src) {
    asm volatile("cp.async.ca.shared.global [%0], [%1], 4;" :: "r"(dst), "l"(src));
}
__device__ __forceinline__ void cp_commit() { asm volatile("cp.async.commit_group;"); }
template <int N> __device__ __forceinline__ void cp_wait() {
    asm volatile("cp.async.wait_group %0;" :: "n"(N));
}
__device__ __forceinline__ unsigned long long ffma2(unsigned long long a,
                                                    unsigned long long b,
                                                    unsigned long long c) {
    unsigned long long d;
    asm("fma.rn.f32x2 %0, %1, %2, %3;" : "=l"(d) : "l"(a), "l"(b), "l"(c));
    return d;
}
__device__ __forceinline__ unsigned long long packdup(float x) {
    unsigned long long d;
    asm("mov.b64 %0, {%1, %1};" : "=l"(d) : "f"(x));
    return d;
}
__device__ __forceinline__ void unpack2(unsigned long long v, float& lo, float& hi) {
    asm("mov.b64 {%0, %1}, %2;" : "=f"(lo), "=f"(hi) : "l"(v));
}

// ---------------- k2 smem layout (bytes) ----------------
#define OFF_A    0                        // dup A: 48k x 128 rows x 8B = 49152
#define OFF_B    49152                    // 2 x (48k x 128 cols x 4B)  = 49152
#define OFF_SQ   98304                    // 2 x 512
#define OFF_LIST 99328                    // 128 rows x 80B (9 slots x 8B, padded)
#define OFF_THR  109568                   // 128 x 4
#define SMEM_K2  110080

// ======================================================================
// K1: normalize; emit g_xt / g_xtd (k-major), g_nodes, sq, deg=0.
// ======================================================================
__global__ __launch_bounds__(128) void k1_normalize(const float* __restrict__ x) {
    __shared__ float s[128 * 49];
    __shared__ float s_mn[128];
    const int tid  = threadIdx.x;
    const int n0g  = blockIdx.x * 128;
    const int b    = n0g >> 12;
    const int nloc = n0g & (NPIX - 1);

    const float* xb = x + (size_t)b * CCH * NPIX + nloc;
    #pragma unroll
    for (int c = 0; c < CCH; c++)
        s[tid * 49 + c] = xb[(size_t)c * NPIX + tid];

    float ss = 0.f;
    #pragma unroll
    for (int c = 0; c < CCH; c++) { float v = s[tid * 49 + c]; ss += v * v; }
    float mn = fmaxf(sqrtf(ss), 1e-12f);
    s_mn[tid] = mn;
    float sqv = 0.f;
    #pragma unroll
    for (int c = 0; c < CCH; c++) { float v = s[tid * 49 + c] / mn; sqv += v * v; }
    g_sq[n0g + tid]  = sqv;
    g_deg[n0g + tid] = 0;
    __syncthreads();

    // k-major normalized + duplicated copy (exact division, matches reference)
    #pragma unroll
    for (int c = 0; c < CCH; c++) {
        const float v = s[tid * 49 + c] / s_mn[tid];
        const int   a = (b * CCH + c) * NPIX + nloc + tid;
        g_xt[a]  = v;
        g_xtd[a] = make_float2(v, v);
    }

    // raw node-major copy (k5)
    float* nodes_f = (float*)g_nodes;
    #pragma unroll
    for (int it = 0; it < 48; it++) {
        int idx = it * 128 + tid;
        int q = idx / 48, rr = idx - q * 48;
        nodes_f[(size_t)n0g * 48 + idx] = s[q * 49 + rr];
    }
}

// ======================================================================
// K2: register-blocked fp32x2 SGEMM (128x128x48 tiles) + min-fold
//     screened exact top-9 selection.  Thread = 4 rows x 16 cols.
// ======================================================================
__global__ __launch_bounds__(256, 2) void k2_knn() {
    extern __shared__ __align__(16) char smem[];
    const uint32_t sb = smem_u32(smem);
    const int tid  = threadIdx.x;
    const int lane = tid & 31;
    const int cg   = tid & 7;           // column group within row-quad set
    const int rq   = tid >> 3;          // row quad (0..31)
    const int rqw  = lane >> 3;         // row-quad within warp (0..3)
    const uint32_t gmask = 0xFFu << (rqw * 8);
    const int b   = blockIdx.x >> 5;
    const int rt  = blockIdx.x & 31;
    const int rowbase = b * NPIX + rt * 128;

    // init per-row lists + thresholds
    for (int i = tid; i < 128 * 9; i += 256) {
        const int row = i / 9, sl = i - row * 9;
        *(float*)(smem + OFF_LIST + row * 80 + sl * 8)     = __int_as_float(0x7f800000);
        *(int*)  (smem + OFF_LIST + row * 80 + sl * 8 + 4) = 0x7fffffff;
    }
    if (tid < 128) *(float*)(smem + OFF_THR + tid * 4) = __int_as_float(0x7f800000);

    // prologue: A-dup strip + B tile 0 + sq0
    {
        #pragma unroll
        for (int i = 0; i < 12; i++) {
            const int c = tid + i * 256;          // 3072 chunks of 16B
            const int k = c >> 6, rp = c & 63;    // 64 chunks per k-row
            cp16(sb + OFF_A + (uint32_t)(k * 1024 + rp * 16),
                 g_xtd + (size_t)(b * CCH + k) * NPIX + rt * 128 + rp * 2);
        }
        #pragma unroll
        for (int i = 0; i < 6; i++) {
            const int c = tid + i * 256;          // 1536 chunks
            const int k = c >> 5, p = c & 31;
            cp16(sb + OFF_B + (uint32_t)(k * 512 + p * 16),
                 g_xt + (size_t)(b * CCH + k) * NPIX + p * 4);
        }
        if (tid < 128) cp4(sb + OFF_SQ + tid * 4, g_sq + b * NPIX + tid);
        cp_commit();
    }

    float thr[4];
    #pragma unroll
    for (int r = 0; r < 4; r++) thr[r] = __int_as_float(0x7f800000);
    const unsigned long long NEG2 = packdup(-2.0f);

    #pragma unroll 1
    for (int t = 0; t < 32; t++) {
        const int buf = t & 1;
        cp_wait<0>();
        __syncthreads();

        if (t < 31) {
            const int col0 = (t + 1) * 128;
            const uint32_t dstB = sb + OFF_B + (buf ^ 1) * 24576;
            #pragma unroll
            for (int i = 0; i < 6; i++) {
                const int c = tid + i * 256;
                const int k = c >> 5, p = c & 31;
                cp16(dstB + (uint32_t)(k * 512 + p * 16),
                     g_xt + (size_t)(b * CCH + k) * NPIX + col0 + p * 4);
            }
            if (tid < 128) cp4(sb + OFF_SQ + (buf ^ 1) * 512 + tid * 4,
                               g_sq + b * NPIX + col0 + tid);
            cp_commit();
        }

        // ---- GEMM: C[4 rows][4 j][2 pairs], K=48, zero-mov inner loop ----
        unsigned long long C[4][4][2];
        #pragma unroll
        for (int r = 0; r < 4; r++)
            #pragma unroll
            for (int j = 0; j < 4; j++) { C[r][j][0] = 0ull; C[r][j][1] = 0ull; }

        const char* Abase = smem + OFF_A + (uint32_t)rq * 32;
        const char* Bbase = smem + OFF_B + buf * 24576 + (uint32_t)cg * 16;
        #pragma unroll 8
        for (int k = 0; k < 48; k++) {
            const ulonglong2 a01 = *(const ulonglong2*)(Abase + k * 1024);
            const ulonglong2 a23 = *(const ulonglong2*)(Abase + k * 1024 + 16);
            #pragma unroll
            for (int j = 0; j < 4; j++) {
                const ulonglong2 bv = *(const ulonglong2*)(Bbase + k * 512 + j * 128);
                C[0][j][0] = ffma2(a01.x, bv.x, C[0][j][0]);
                C[0][j][1] = ffma2(a01.x, bv.y, C[0][j][1]);
                C[1][j][0] = ffma2(a01.y, bv.x, C[1][j][0]);
                C[1][j][1] = ffma2(a01.y, bv.y, C[1][j][1]);
                C[2][j][0] = ffma2(a23.x, bv.x, C[2][j][0]);
                C[2][j][1] = ffma2(a23.x, bv.y, C[2][j][1]);
                C[3][j][0] = ffma2(a23.y, bv.x, C[3][j][0]);
                C[3][j][1] = ffma2(a23.y, bv.y, C[3][j][1]);
            }
        }

        // ---- epilogue: scalar min-fold screen, rare exact insert ----
        ulonglong2 sq2[4];
        #pragma unroll
        for (int j = 0; j < 4; j++)
            sq2[j] = *(const ulonglong2*)(smem + OFF_SQ + buf * 512 + j * 128 + cg * 16);

        const int tbase = b * NPIX + t * 128;
        #pragma unroll
        for (int r = 0; r < 4; r++) {
            float rowmin = __int_as_float(0x7f800000);
            #pragma unroll
            for (int j = 0; j < 4; j++) {
                float l0, h0, l1, h1;
                unpack2(ffma2(C[r][j][0], NEG2, sq2[j].x), l0, h0);
                unpack2(ffma2(C[r][j][1], NEG2, sq2[j].y), l1, h1);
                rowmin = fminf(rowmin, fminf(fminf(l0, h0), fminf(l1, h1)));
            }
            const bool hit = rowmin < thr[r];
            const uint32_t bal = __ballot_sync(0xffffffffu, hit);
            uint32_t grp = (bal >> (rqw * 8)) & 0xffu;
            if (grp) {
                const int lr = (rq << 2) + r;                 // local row 0..127
                while (grp) {
                    const int s = __ffs(grp) - 1;
                    grp &= grp - 1;
                    if ((lane & 7) == s) {
                        float th = *(volatile float*)(smem + OFF_THR + lr * 4);
                        #pragma unroll
                        for (int j = 0; j < 4; j++) {
                            #pragma unroll
                            for (int p = 0; p < 2; p++) {
                                float d0, d1;
                                unpack2(ffma2(C[r][j][p], NEG2,
                                              p ? sq2[j].y : sq2[j].x), d0, d1);
                                const int col0 = tbase + j * 32 + cg * 4 + p * 2;
                                #pragma unroll
                                for (int e = 0; e < 2; e++) {
                                    const float dv = e ? d1 : d0;
                                    if (dv < th) {
                                        float cd = dv; int ci = col0 + e;
                                        #pragma unroll
                                        for (int sl = 0; sl < KNN; sl++) {
                                            float* dp = (float*)(smem + OFF_LIST
                                                         + lr * 80 + sl * 8);
                                            int*   ip = (int*)(dp + 1);
                                            const float od = *dp; const int oi = *ip;
                                            const bool sw = cd < od;
                                            *dp = sw ? cd : od; *ip = sw ? ci : oi;
                                            cd = sw ? od : cd;  ci = sw ? oi : ci;
                                        }
                                        th = *(float*)(smem + OFF_LIST + lr * 80 + 64);
                                    }
                                }
                            }
                        }
                        *(volatile float*)(smem + OFF_THR + lr * 4) = th;
                    }
                    __syncwarp(gmask);
                }
                thr[r] = *(volatile float*)(smem + OFF_THR + lr * 4);
            }
        }
    }

    // ---- writeout: lists -> g_knn + degree atomics ----
    __syncwarp();
    const int wrp = tid >> 5;
    for (int rr = 0; rr < 16; rr++) {
        const int lr  = wrp * 16 + rr;
        const int row = rowbase + lr;
        if (lane < KNN) {
            const int idx = *(int*)(smem + OFF_LIST + lr * 80 + lane * 8 + 4);
            g_knn[(size_t)row * KNN + lane] = idx;
            if (!(row == NB - 1 && lane == KNN - 1))
                atomicAdd(&g_deg[idx], 1);
        }
    }
}

// ======================================================================
// K5: fused Tx1 gather + both GEMMs + bias.
// ======================================================================
__global__ __launch_bounds__(192) void k5_output(const float* __restrict__ W0,
                                                 const float* __restrict__ W1,
                                                 const float* __restrict__ bias,
                                                 float* __restrict__ out) {
    const int node0 = blockIdx.x * 4;
    const int ln = threadIdx.x / 48;
    const int c  = threadIdx.x - ln * 48;
    const int i  = node0 + ln;

    __shared__ float t1[4][48];
    __shared__ int   ssrc[4][KNN];
    __shared__ float sdi[4][KNN];

    if (threadIdx.x < 4 * KNN) {
        const int l = threadIdx.x / KNN, k = threadIdx.x - l * KNN;
        const int e = (node0 + l) * KNN + k;
        const int s = g_knn[e];
        ssrc[l][k] = s;
        float di = 0.f;
        const int dg = g_deg[s];
        if (dg > 0 && e != NB * KNN - 1) di = rsqrtf((float)dg);
        sdi[l][k] = di;
    }
    __syncthreads();

    const float* nodes = (const float*)g_nodes;
    float acc = 0.f;
    #pragma unroll
    for (int k = 0; k < KNN; k++)
        acc += sdi[ln][k] * nodes[(size_t)ssrc[ln][k] * 48 + c];

    const int dgi = g_deg[i];
    const float dinv_i = (dgi > 0) ? rsqrtf((float)dgi) : 0.f;
    t1[ln][c] = -dinv_i * acc;
    __syncthreads();

    float o = bias[c];
    const float* nrow = nodes + (size_t)i * 48;
    #pragma unroll
    for (int cc = 0; cc < 48; cc++)
        o += nrow[cc] * W0[cc * 48 + c] + t1[ln][cc] * W1[cc * 48 + c];
    out[(size_t)i * 48 + c] = o;
}

// ======================================================================
extern "C" void kernel_launch(void* const* d_in, const int* in_sizes, int n_in,
                              void* d_out, int out_size) {
    const float* x    = (const float*)d_in[0];
    const float* W0   = (const float*)d_in[1];
    const float* W1   = (const float*)d_in[2];
    const float* bias = (const float*)d_in[3];
    float* out = (float*)d_out;

    cudaFuncSetAttribute(k2_knn, cudaFuncAttributeMaxDynamicSharedMemorySize, SMEM_K2);

    k1_normalize<<<NB / 128, 128>>>(x);
    k2_knn<<<BATCH * 32, 256, SMEM_K2>>>();
    k5_output<<<NB / 4, 192>>>(W0, W1, bias, out);
}

// round 10
// speedup vs baseline: 3.2277x; 3.2277x over previous
#include <cuda_runtime.h>
#include <cstdint>

#define BATCH 8
#define CCH   48
#define NPIX  4096
#define NB    32768
#define KNN   9

// ---------------- device scratch ----------------
__device__ float  g_xt [BATCH * CCH * NPIX];   // normalized, k-major (B tiles)
__device__ float2 g_xtd[BATCH * CCH * NPIX];   // normalized, duplicated pairs (A tiles)
__device__ float4 g_nodes[NB * 12];            // raw, node-major (k5)
__device__ float  g_sq[NB];                    // sum(xn^2)
__device__ int    g_knn[NB * KNN];
__device__ int    g_deg[NB];

// ---------------- helpers ----------------
__device__ __forceinline__ uint32_t smem_u32(const void* p) {
    uint32_t a;
    asm("{ .reg .u64 t; cvta.to.shared.u64 t, %1; cvt.u32.u64 %0, t; }" : "=r"(a) : "l"(p));
    return a;
}
__device__ __forceinline__ void cp16(uint32_t dst, const void* src) {
    asm volatile("cp.async.cg.shared.global [%0], [%1], 16;" :: "r"(dst), "l"(src));
}
__device__ __forceinline__ void cp4(uint32_t dst, const void* src) {
    asm volatile("cp.async.ca.shared.global [%0], [%1], 4;" :: "r"(dst), "l"(src));
}
__device__ __forceinline__ void cp_commit() { asm volatile("cp.async.commit_group;"); }
template <int N> __device__ __forceinline__ void cp_wait() {
    asm volatile("cp.async.wait_group %0;" :: "n"(N));
}
__device__ __forceinline__ unsigned long long ffma2(unsigned long long a,
                                                    unsigned long long b,
                                                    unsigned long long c) {
    unsigned long long d;
    asm("fma.rn.f32x2 %0, %1, %2, %3;" : "=l"(d) : "l"(a), "l"(b), "l"(c));
    return d;
}
__device__ __forceinline__ unsigned long long packdup(float x) {
    unsigned long long d;
    asm("mov.b64 %0, {%1, %1};" : "=l"(d) : "f"(x));
    return d;
}
__device__ __forceinline__ void unpack2(unsigned long long v, float& lo, float& hi) {
    asm("mov.b64 {%0, %1}, %2;" : "=f"(lo), "=f"(hi) : "l"(v));
}

// ---------------- k2 smem layout (bytes) ----------------
#define OFF_A    0                        // dup A: 48k x 128 rows x 8B = 49152
#define OFF_B    49152                    // 2 x (48k x 128 cols x 4B) = 49152
#define OFF_SQ   98304                    // 2 x 512
#define SMEM_K2  99328
// merge scratch overlays OFF_B after the main loop (B dead by then)

// ======================================================================
// K1: normalize; emit g_xt / g_xtd (k-major), g_nodes, sq, deg=0.
// ======================================================================
__global__ __launch_bounds__(128) void k1_normalize(const float* __restrict__ x) {
    __shared__ float s[128 * 49];
    __shared__ float s_mn[128];
    const int tid  = threadIdx.x;
    const int n0g  = blockIdx.x * 128;
    const int b    = n0g >> 12;
    const int nloc = n0g & (NPIX - 1);

    const float* xb = x + (size_t)b * CCH * NPIX + nloc;
    #pragma unroll
    for (int c = 0; c < CCH; c++)
        s[tid * 49 + c] = xb[(size_t)c * NPIX + tid];

    float ss = 0.f;
    #pragma unroll
    for (int c = 0; c < CCH; c++) { float v = s[tid * 49 + c]; ss += v * v; }
    float mn = fmaxf(sqrtf(ss), 1e-12f);
    s_mn[tid] = mn;
    float sqv = 0.f;
    #pragma unroll
    for (int c = 0; c < CCH; c++) { float v = s[tid * 49 + c] / mn; sqv += v * v; }
    g_sq[n0g + tid]  = sqv;
    g_deg[n0g + tid] = 0;
    __syncthreads();

    #pragma unroll
    for (int c = 0; c < CCH; c++) {
        const float v = s[tid * 49 + c] / s_mn[tid];
        const int   a = (b * CCH + c) * NPIX + nloc + tid;
        g_xt[a]  = v;
        g_xtd[a] = make_float2(v, v);
    }

    float* nodes_f = (float*)g_nodes;
    #pragma unroll
    for (int it = 0; it < 48; it++) {
        int idx = it * 128 + tid;
        int q = idx / 48, rr = idx - q * 48;
        nodes_f[(size_t)n0g * 48 + idx] = s[q * 49 + rr];
    }
}

// ======================================================================
// K2: fp32x2 GEMM, thread = 1 row x 64 cols (B operand warp-uniform),
//     register-resident exact top-9 per (row, col-half).
// ======================================================================
__global__ __launch_bounds__(256, 2) void k2_knn() {
    extern __shared__ __align__(16) char smem[];
    const int tid  = threadIdx.x;
    const int row  = tid & 127;          // local row this thread owns
    const int half = tid >> 7;           // column half (0: cols 0..63, 1: 64..127)
    const int b    = blockIdx.x >> 5;
    const int rt   = blockIdx.x & 31;
    const int rowbase = b * NPIX + rt * 128;
    const uint32_t sb = smem_u32(smem);

    // prologue: A-dup strip + B tile 0 + sq0
    {
        #pragma unroll
        for (int i = 0; i < 12; i++) {
            const int c = tid + i * 256;          // 3072 chunks of 16B
            const int k = c >> 6, rp = c & 63;
            cp16(sb + OFF_A + (uint32_t)(k * 1024 + rp * 16),
                 g_xtd + (size_t)(b * CCH + k) * NPIX + rt * 128 + rp * 2);
        }
        #pragma unroll
        for (int i = 0; i < 6; i++) {
            const int c = tid + i * 256;          // 1536 chunks
            const int k = c >> 5, p = c & 31;
            cp16(sb + OFF_B + (uint32_t)(k * 512 + p * 16),
                 g_xt + (size_t)(b * CCH + k) * NPIX + p * 4);
        }
        if (tid < 128) cp4(sb + OFF_SQ + tid * 4, g_sq + b * NPIX + tid);
        cp_commit();
    }

    // register top-9 (ascending d), strict < keeps lowest col on ties
    float d9[KNN]; int i9[KNN];
    #pragma unroll
    for (int k = 0; k < KNN; k++) { d9[k] = __int_as_float(0x7f800000); i9[k] = 0x7fffffff; }
    float thr = __int_as_float(0x7f800000);
    const unsigned long long NEG2 = packdup(-2.0f);

    #pragma unroll 1
    for (int t = 0; t < 32; t++) {
        const int buf = t & 1;
        cp_wait<0>();
        __syncthreads();

        if (t < 31) {
            const int col0 = (t + 1) * 128;
            const uint32_t dstB = sb + OFF_B + (buf ^ 1) * 24576;
            #pragma unroll
            for (int i = 0; i < 6; i++) {
                const int c = tid + i * 256;
                const int k = c >> 5, p = c & 31;
                cp16(dstB + (uint32_t)(k * 512 + p * 16),
                     g_xt + (size_t)(b * CCH + k) * NPIX + col0 + p * 4);
            }
            if (tid < 128) cp4(sb + OFF_SQ + (buf ^ 1) * 512 + tid * 4,
                               g_sq + b * NPIX + col0 + tid);
            cp_commit();
        }

        // ---- GEMM: C[32] packed pairs = 64 cols of one row, K=48 ----
        unsigned long long C[32];
        #pragma unroll
        for (int i = 0; i < 32; i++) C[i] = 0ull;

        const char* Abase = smem + OFF_A + (uint32_t)row * 8;
        const char* Bbase = smem + OFF_B + buf * 24576 + (uint32_t)half * 256;
        #pragma unroll 1
        for (int k = 0; k < 48; k++) {
            const unsigned long long a = *(const unsigned long long*)(Abase + k * 1024);
            const char* bk = Bbase + k * 512;
            #pragma unroll
            for (int q = 0; q < 16; q++) {
                const ulonglong2 bv = *(const ulonglong2*)(bk + q * 16);
                C[2 * q]     = ffma2(a, bv.x, C[2 * q]);
                C[2 * q + 1] = ffma2(a, bv.y, C[2 * q + 1]);
            }
        }

        // ---- epilogue: d = sq - 2*dot; screen per 4 cols; register insert ----
        const char* sqb = smem + OFF_SQ + buf * 512 + (uint32_t)half * 256;
        const int gbase = b * NPIX + t * 128 + half * 64;
        #pragma unroll
        for (int q = 0; q < 16; q++) {
            const ulonglong2 s2 = *(const ulonglong2*)(sqb + q * 16);
            float d0, d1, d2, d3;
            unpack2(ffma2(C[2 * q],     NEG2, s2.x), d0, d1);
            unpack2(ffma2(C[2 * q + 1], NEG2, s2.y), d2, d3);
            const float m = fminf(fminf(d0, d1), fminf(d2, d3));
            if (m < thr) {
                #pragma unroll
                for (int e = 0; e < 4; e++) {
                    const float dv = (e == 0) ? d0 : (e == 1) ? d1 : (e == 2) ? d2 : d3;
                    if (dv < thr) {
                        float cd = dv; int ci = gbase + q * 4 + e;
                        #pragma unroll
                        for (int sl = 0; sl < KNN; sl++) {
                            const bool sw = cd < d9[sl];
                            const float td = d9[sl]; const int ti = i9[sl];
                            d9[sl] = sw ? cd : td;  i9[sl] = sw ? ci : ti;
                            cd     = sw ? td : cd;  ci     = sw ? ti : ci;
                        }
                        thr = d9[KNN - 1];
                    }
                }
            }
        }
    }

    // ---- merge two half-row lists (scratch overlays dead B buffer) ----
    __syncthreads();
    float* sc_d = (float*)(smem + OFF_B);          // [row][half][9]
    int*   sc_i = (int*)(smem + OFF_B + 128 * 2 * KNN * 4);
    #pragma unroll
    for (int k = 0; k < KNN; k++) {
        sc_d[(row * 2 + half) * KNN + k] = d9[k];
        sc_i[(row * 2 + half) * KNN + k] = i9[k];
    }
    __syncthreads();

    if (tid < 128) {
        const int gr = rowbase + tid;
        const float* da = sc_d + (tid * 2) * KNN;      const int* ia = sc_i + (tid * 2) * KNN;
        const float* db = sc_d + (tid * 2 + 1) * KNN;  const int* ib = sc_i + (tid * 2 + 1) * KNN;
        int ha = 0, hb = 0;
        #pragma unroll
        for (int k = 0; k < KNN; k++) {
            const float ad = da[ha]; const int ai = ia[ha];
            const float bd = db[hb]; const int bi = ib[hb];
            const bool takeA = (ad < bd) || (ad == bd && ai < bi);
            const int sel = takeA ? ai : bi;
            g_knn[(size_t)gr * KNN + k] = sel;
            if (!(gr == NB - 1 && k == KNN - 1))
                atomicAdd(&g_deg[sel], 1);
            if (takeA) ha++; else hb++;
        }
    }
}

// ======================================================================
// K5: fused Tx1 gather + both GEMMs + bias.
// ======================================================================
__global__ __launch_bounds__(192) void k5_output(const float* __restrict__ W0,
                                                 const float* __restrict__ W1,
                                                 const float* __restrict__ bias,
                                                 float* __restrict__ out) {
    const int node0 = blockIdx.x * 4;
    const int ln = threadIdx.x / 48;
    const int c  = threadIdx.x - ln * 48;
    const int i  = node0 + ln;

    __shared__ float t1[4][48];
    __shared__ int   ssrc[4][KNN];
    __shared__ float sdi[4][KNN];

    if (threadIdx.x < 4 * KNN) {
        const int l = threadIdx.x / KNN, k = threadIdx.x - l * KNN;
        const int e = (node0 + l) * KNN + k;
        const int s = g_knn[e];
        ssrc[l][k] = s;
        float di = 0.f;
        const int dg = g_deg[s];
        if (dg > 0 && e != NB * KNN - 1) di = rsqrtf((float)dg);
        sdi[l][k] = di;
    }
    __syncthreads();

    const float* nodes = (const float*)g_nodes;
    float acc = 0.f;
    #pragma unroll
    for (int k = 0; k < KNN; k++)
        acc += sdi[ln][k] * nodes[(size_t)ssrc[ln][k] * 48 + c];

    const int dgi = g_deg[i];
    const float dinv_i = (dgi > 0) ? rsqrtf((float)dgi) : 0.f;
    t1[ln][c] = -dinv_i * acc;
    __syncthreads();

    float o = bias[c];
    const float* nrow = nodes + (size_t)i * 48;
    #pragma unroll
    for (int cc = 0; cc < 48; cc++)
        o += nrow[cc] * W0[cc * 48 + c] + t1[ln][cc] * W1[cc * 48 + c];
    out[(size_t)i * 48 + c] = o;
}

// ======================================================================
extern "C" void kernel_launch(void* const* d_in, const int* in_sizes, int n_in,
                              void* d_out, int out_size) {
    const float* x    = (const float*)d_in[0];
    const float* W0   = (const float*)d_in[1];
    const float* W1   = (const float*)d_in[2];
    const float* bias = (const float*)d_in[3];
    float* out = (float*)d_out;

    cudaFuncSetAttribute(k2_knn, cudaFuncAttributeMaxDynamicSharedMemorySize, SMEM_K2);

    k1_normalize<<<NB / 128, 128>>>(x);
    k2_knn<<<BATCH * 32, 256, SMEM_K2>>>();
    k5_output<<<NB / 4, 192>>>(W0, W1, bias, out);
}